// round 8
// baseline (speedup 1.0000x reference)
#include <cuda_runtime.h>

// Problem constants
#define NPT   4096      // B*H*W = 4*32*32 output points
#define NOC   64        // output channels
#define NFEAT 576       // IC*K*K unfolded features
#define NGRP  144       // 4-feature groups
#define NCH   5         // subarray chunks (29,29,29,29,28 groups)
#define PM    1792      // points handled by the MMA role (multiple of 16)
#define MMA_BLOCKS ((PM / 16) * 2)                  // 224
#define DP_OBLK 4
#define DP_PTS  (NPT - PM)                          // 2304
#define DP_PB   (DP_PTS / 128)                      // 18
#define DP_BLOCKS (DP_PB * (NOC / DP_OBLK) * NCH)   // 18*16*5 = 1440

// Scratch (no allocations allowed -> device globals)
__device__ float    g_maxabs;
__device__ unsigned g_wpos[NOC * NFEAT];        // [o][t][g] packed bytes (dp4a B)
__device__ unsigned g_wneg[NOC * NFEAT];
__device__ unsigned g_wpk[NCH * 8 * NOC * 32];  // [ch][tpn][oc][kw] (mma B), pads 0
__device__ uint4    g_sv2[NGRP * NPT];          // [g][pt] stream words s0..s3
__device__ int      g_part[NCH * NOC * NPT];    // per-chunk partials (dp4a half)

// ---------------------------------------------------------------- max |w|
__global__ void k_maxabs(const float* __restrict__ w, int n) {
    __shared__ float red[32];
    float m = 0.f;
    for (int i = threadIdx.x; i < n; i += blockDim.x)
        m = fmaxf(m, fabsf(w[i]));
    for (int o = 16; o; o >>= 1) m = fmaxf(m, __shfl_xor_sync(0xffffffffu, m, o));
    if ((threadIdx.x & 31) == 0) red[threadIdx.x >> 5] = m;
    __syncthreads();
    if (threadIdx.x < 32) {
        int nw = (blockDim.x + 31) >> 5;
        m = (threadIdx.x < nw) ? red[threadIdx.x] : 0.f;
        for (int o = 16; o; o >>= 1) m = fmaxf(m, __shfl_xor_sync(0xffffffffu, m, o));
        if (threadIdx.x == 0) g_maxabs = (m > 0.f) ? m : 1.f;
    }
}

// ---------------- weight bit-slicing: both dp4a and mma layouts
__global__ void k_weights(const float* __restrict__ w) {
    int idx = blockIdx.x * blockDim.x + threadIdx.x;   // NOC * NCH * 32
    if (idx >= NOC * NCH * 32) return;
    int kw = idx & 31;
    int ch = (idx >> 5) % NCH;
    int o  = idx / (NCH * 32);
    int ng = (ch == 4) ? 28 : 29;
    unsigned pw[4] = {0,0,0,0}, nw[4] = {0,0,0,0};
    if (kw < ng) {
        float ma = g_maxabs;
        int g = ch * 29 + kw;
#pragma unroll
        for (int j = 0; j < 4; j++) {
            float r  = w[o * NFEAT + 4 * g + j];
            float wp = fmaxf(r, 0.f);
            float wn = fmaxf(-r, 0.f);
            int pi = (int)rintf(__fdiv_rn(wp, ma) * 255.f);
            int ni = (int)rintf(__fdiv_rn(wn, ma) * 255.f);
#pragma unroll
            for (int t = 0; t < 4; t++) {
                pw[t] |= (unsigned)((pi >> (2 * t)) & 3) << (8 * j);
                nw[t] |= (unsigned)((ni >> (2 * t)) & 3) << (8 * j);
            }
        }
    }
#pragma unroll
    for (int t = 0; t < 4; t++) {
        g_wpk[((ch * 8 + t) * NOC + o) * 32 + kw]     = pw[t];
        g_wpk[((ch * 8 + 4 + t) * NOC + o) * 32 + kw] = nw[t];
    }
    if (kw < ng) {
        int g = ch * 29 + kw;
#pragma unroll
        for (int t = 0; t < 4; t++) {
            g_wpos[o * NFEAT + t * NGRP + g] = pw[t];
            g_wneg[o * NFEAT + t * NGRP + g] = nw[t];
        }
    }
}

// -------------- input quantize + unfold + bit-stream pack ([g][pt] uint4)
__global__ void k_streams(const float* __restrict__ x) {
    int id = blockIdx.x * blockDim.x + threadIdx.x;   // NPT*NGRP
    if (id >= NPT * NGRP) return;
    int pt = id & (NPT - 1);
    int g  = id >> 12;
    int b = pt >> 10, p = pt & 1023, h = p >> 5, wc = p & 31;
    unsigned sw0 = 0, sw1 = 0, sw2 = 0, sw3 = 0;
#pragma unroll
    for (int j = 0; j < 4; j++) {
        int f = 4 * g + j;
        int c = f / 9, rem = f - 9 * c, kh = rem / 3, kw = rem - 3 * (rem / 3);
        int y = h + kh - 1, xx = wc + kw - 1;
        float v = 0.f;
        if ((unsigned)y < 32u && (unsigned)xx < 32u)
            v = x[((b * 64 + c) * 32 + y) * 32 + xx];
        v = fminf(fmaxf(v, -8.f), 7.9375f);
        int q = ((int)rintf(v * 16.f)) & 255;
        sw0 |= (unsigned)( q        & 3) << (8 * j);
        sw1 |= (unsigned)((q >> 2)  & 3) << (8 * j);
        sw2 |= (unsigned)((q >> 4)  & 3) << (8 * j);
        sw3 |= (unsigned)((q >> 6)  & 3) << (8 * j);
    }
    g_sv2[g * NPT + pt] = make_uint4(sw0, sw1, sw2, sw3);
}

// ---------------------------------------------------------------- mma op
__device__ __forceinline__ void mma_s8(int d[4], unsigned a0, unsigned a1,
                                       unsigned a2, unsigned a3,
                                       unsigned b0, unsigned b1) {
    asm volatile(
        "mma.sync.aligned.m16n8k32.row.col.s32.s8.s8.s32 "
        "{%0,%1,%2,%3}, {%4,%5,%6,%7}, {%8,%9}, {%0,%1,%2,%3};"
        : "+r"(d[0]), "+r"(d[1]), "+r"(d[2]), "+r"(d[3])
        : "r"(a0), "r"(a1), "r"(a2), "r"(a3), "r"(b0), "r"(b1));
}

// =========================== hybrid main kernel ===========================
// 128 threads. Blocks [0, MMA_BLOCKS): IMMA role, pts [0, PM), fragment-order
// smem staging (A: LDS.128 / (s,kb); B: 2x LDS.32 / (t,kb)).
// Blocks [MMA_BLOCKS, +DP_BLOCKS): dp4a role, pts [PM, NPT).
__global__ __launch_bounds__(128, 4) void k_hybrid(float* __restrict__ out) {
    __shared__ union {
        struct {
            unsigned a[4][4][32][4];     // [s][kb][lane][e]      8 KB
            unsigned b[8][4][4][2][32];  // [tpn][kb][warp][bsel][lane] 16 KB
        } m;
        struct { unsigned w[DP_OBLK][29][8]; } d;
    } sm;
    const int tid = threadIdx.x;

    if (blockIdx.x < MMA_BLOCKS) {
        // ---------------- MMA role: tile 16 pts x 32 oc, all chunks ----------------
        const int warp = tid >> 5, lane = tid & 31;
        const int gid  = lane >> 2, tig = lane & 3;
        const int ptbase = (blockIdx.x >> 1) << 4;
        const int ocbase = (blockIdx.x & 1) << 5;

        int diffd[4] = {0, 0, 0, 0};

        for (int c = 0; c < NCH; c++) {
            const int ng = (c == 4) ? 28 : 29;
            __syncthreads();
            // stage A in fragment order
            for (int i = tid; i < 16 * 32; i += 128) {
                int pt = i >> 5, kw = i & 31;
                uint4 v = make_uint4(0, 0, 0, 0);
                if (kw < ng) v = g_sv2[(c * 29 + kw) * NPT + ptbase + pt];
                int ln = (pt & 7) * 4 + (kw & 3);
                int kb = kw >> 3;
                int e  = ((pt >> 3) & 1) | (((kw >> 2) & 1) << 1);
                sm.m.a[0][kb][ln][e] = v.x; sm.m.a[1][kb][ln][e] = v.y;
                sm.m.a[2][kb][ln][e] = v.z; sm.m.a[3][kb][ln][e] = v.w;
            }
            // stage B in fragment order (uint4 source, pads already zero)
            for (int i = tid; i < 8 * 32 * 8; i += 128) {
                int tpn = i >> 8, rest = i & 255;
                int oc = rest >> 3, kw4 = (rest & 7) * 4;
                uint4 v = *(const uint4*)&g_wpk[((c * 8 + tpn) * NOC + ocbase + oc) * 32 + kw4];
                int w = oc >> 3, g8 = (oc & 7) * 4;
                int kb = kw4 >> 3, bsel = (kw4 >> 2) & 1;
                unsigned* dst = &sm.m.b[tpn][kb][w][bsel][g8];
                dst[0] = v.x; dst[1] = v.y; dst[2] = v.z; dst[3] = v.w;
            }
            __syncthreads();

#pragma unroll
            for (int pn = 0; pn < 2; pn++) {
                int acc[16][4];
#pragma unroll
                for (int i = 0; i < 16; i++)
#pragma unroll
                    for (int e = 0; e < 4; e++) acc[i][e] = 0;

#pragma unroll
                for (int kb = 0; kb < 4; kb++) {
                    uint4 av[4];
#pragma unroll
                    for (int s = 0; s < 4; s++)
                        av[s] = *(const uint4*)&sm.m.a[s][kb][lane][0];
#pragma unroll
                    for (int t = 0; t < 4; t++) {
                        unsigned b0 = sm.m.b[pn * 4 + t][kb][warp][0][lane];
                        unsigned b1 = sm.m.b[pn * 4 + t][kb][warp][1][lane];
#pragma unroll
                        for (int s = 0; s < 4; s++)
                            mma_s8(acc[s * 4 + t], av[s].x, av[s].y, av[s].z, av[s].w, b0, b1);
                    }
                }
#pragma unroll
                for (int s = 0; s < 4; s++)
#pragma unroll
                    for (int t = 0; t < 4; t++) {
                        int sh = 2 * (s + t);
#pragma unroll
                        for (int e = 0; e < 4; e++) {
                            int v = min(acc[s * 4 + t][e], 31) << sh;
                            diffd[e] += pn ? -v : v;
                        }
                    }
            }
        }

        const float scale = g_maxabs * (1.0f / 255.0f);
        const int oc0 = ocbase + warp * 8 + tig * 2;
#pragma unroll
        for (int e = 0; e < 4; e++) {
            int pt = ptbase + gid + ((e & 2) ? 8 : 0);
            int oc = oc0 + (e & 1);
            int b = pt >> 10, p = pt & 1023;
            out[((b * NOC + oc) << 10) + p] = (float)diffd[e] * scale;
        }
    } else {
        // ---------------- dp4a role: 128 pts x 4 oc x 1 chunk ----------------
        const int bid   = blockIdx.x - MMA_BLOCKS;      // 0..DP_BLOCKS-1
        const int c     = bid / (DP_PB * 16);
        const int rest  = bid % (DP_PB * 16);
        const int obase = (rest % 16) * DP_OBLK;
        const int ptb   = PM + (rest / 16) * 128;
        const int g0    = c * 29;
        const int ng    = (c == 4) ? 28 : 29;
        const int pt    = ptb + tid;

        for (int i = tid; i < DP_OBLK * 29 * 8; i += 128) {
            int r = i & 7, rr = i >> 3;
            int gl = rr % 29, ol = rr / 29;
            unsigned v = 0;
            if (gl < ng) {
                const unsigned* src = (r < 4) ? g_wpos : g_wneg;
                v = src[(obase + ol) * NFEAT + (r & 3) * NGRP + g0 + gl];
            }
            sm.d.w[ol][gl][r] = v;
        }
        __syncthreads();

        const uint4* __restrict__ sv = g_sv2 + g0 * NPT + pt;

#pragma unroll 1
        for (int ol = 0; ol < DP_OBLK; ol++) {
            int accp[16], accn[16];
#pragma unroll
            for (int i = 0; i < 16; i++) { accp[i] = 0; accn[i] = 0; }
#pragma unroll 2
            for (int gl = 0; gl < ng; gl++) {
                uint4 a  = sv[gl * NPT];
                uint4 wp = *reinterpret_cast<const uint4*>(&sm.d.w[ol][gl][0]);
                uint4 wn = *reinterpret_cast<const uint4*>(&sm.d.w[ol][gl][4]);
                const unsigned av[4] = {a.x, a.y, a.z, a.w};
                const unsigned pv[4] = {wp.x, wp.y, wp.z, wp.w};
                const unsigned nv[4] = {wn.x, wn.y, wn.z, wn.w};
#pragma unroll
                for (int s = 0; s < 4; s++)
#pragma unroll
                    for (int t = 0; t < 4; t++) {
                        accp[s * 4 + t] = __dp4a((int)av[s], (int)pv[t], accp[s * 4 + t]);
                        accn[s * 4 + t] = __dp4a((int)av[s], (int)nv[t], accn[s * 4 + t]);
                    }
            }
            int diff = 0;
#pragma unroll
            for (int s = 0; s < 4; s++)
#pragma unroll
                for (int t = 0; t < 4; t++)
                    diff += (min(accp[s * 4 + t], 31) - min(accn[s * 4 + t], 31))
                            << (2 * (s + t));
            g_part[((c * NOC + obase + ol) << 12) + pt] = diff;
        }
    }
}

// -------------------- combine dp4a partials + scale (pts >= PM only)
__global__ void k_final(float* __restrict__ out) {
    int id = blockIdx.x * blockDim.x + threadIdx.x;   // NOC * DP_PTS
    if (id >= NOC * DP_PTS) return;
    int oc = id / DP_PTS;
    int pt = PM + (id % DP_PTS);
    int b = pt >> 10, p = pt & 1023;
    int d = 0;
#pragma unroll
    for (int c = 0; c < NCH; c++)
        d += g_part[((c * NOC + oc) << 12) + pt];
    out[((b * NOC + oc) << 10) + p] = (float)d * (g_maxabs * (1.0f / 255.0f));
}

// zero any tail elements of d_out beyond the conv output
__global__ void k_tail(float* __restrict__ out, int start, int total) {
    int i = start + blockIdx.x * blockDim.x + threadIdx.x;
    if (i < total) out[i] = 0.f;
}

extern "C" void kernel_launch(void* const* d_in, const int* in_sizes, int n_in,
                              void* d_out, int out_size) {
    const float* x = (const float*)d_in[0];   // inputs (4,64,32,32)
    const float* w = (const float*)d_in[1];   // weight (64,64,3,3)
    float* out = (float*)d_out;

    k_maxabs <<<1, 1024>>>(w, in_sizes[1]);
    k_weights<<<(NOC * NCH * 32 + 255) / 256, 256>>>(w);
    k_streams<<<(NPT * NGRP + 255) / 256, 256>>>(x);
    k_hybrid <<<MMA_BLOCKS + DP_BLOCKS, 128>>>(out);
    k_final  <<<(NOC * DP_PTS + 255) / 256, 256>>>(out);

    if (out_size > NPT * NOC) {
        int extra = out_size - NPT * NOC;
        k_tail<<<(extra + 255) / 256, 256>>>(out, NPT * NOC, out_size);
    }
}